// round 17
// baseline (speedup 1.0000x reference)
#include <cuda_runtime.h>
#include <math.h>

// Problem: D [n, 512] fp32 row-major.
//   diag[j]  = sum_i D[i][j]^2
//   out      = 0.001 * sqrt( sum_j (diag[j]-1)^2 )
//
// Fully fused single kernel (R16 best: 86.0us):
//   R17 changes:
//   - occupancy 4 -> 5 CTAs/SM (launch_bounds(256,5), grid 740 = one wave)
//     to push streaming BW toward the 6.9TB/s measured in R10.
//   - 2 shadow accumulators (blockIdx&1) halve per-address atomic depth.

#define D_COLS 512
#define NB     740           // 148 SMs x 5 CTAs = exactly one wave
#define TPB    256           // 128 threads per row, 2 rows per block-iteration
#define PAD    64            // floats between columns: 256B -> distinct L2 lines

// Two padded shadow accumulators: 2 x 512 cols x 64-float stride = 256KB.
__device__ float g_diag_pad[2][D_COLS * PAD];
// Ticket counter for last-block election. Zero at load; reset each run.
__device__ unsigned int g_ticket;

__global__ void __launch_bounds__(TPB, 5)
colsq_fused_kernel(const float* __restrict__ D, int n, float* __restrict__ out) {
    const int tid  = threadIdx.x;
    const int c4   = tid & 127;        // which float4 within the 512-col row
    const int rsub = tid >> 7;         // 0 or 1: which of the block's 2 rows
    const float4* __restrict__ Dv = (const float4*)D;

    float a0 = 0.f, a1 = 0.f, a2 = 0.f, a3 = 0.f;

    const int stride = NB * 2;         // rows advanced per grid iteration
    int row = blockIdx.x * 2 + rsub;

    #pragma unroll 8
    for (; row < n; row += stride) {
        float4 v = Dv[(size_t)row * 128 + c4];
        a0 = fmaf(v.x, v.x, a0);
        a1 = fmaf(v.y, v.y, a1);
        a2 = fmaf(v.z, v.z, a2);
        a3 = fmaf(v.w, v.w, a3);
    }

    // Combine the two row-halves of the block in shared memory.
    __shared__ float4 s[TPB];
    s[tid] = make_float4(a0, a1, a2, a3);
    __syncthreads();

    if (tid < 128) {
        float* shadow = g_diag_pad[blockIdx.x & 1];
        float4 lo = s[tid];
        float4 hi = s[tid + 128];
        // Columns [4*tid, 4*tid+3], each on its own 256B-spaced address.
        atomicAdd(&shadow[(4 * tid + 0) * PAD], lo.x + hi.x);
        atomicAdd(&shadow[(4 * tid + 1) * PAD], lo.y + hi.y);
        atomicAdd(&shadow[(4 * tid + 2) * PAD], lo.z + hi.z);
        atomicAdd(&shadow[(4 * tid + 3) * PAD], lo.w + hi.w);
    }

    // Order this block's RED ops before its ticket increment.
    __threadfence();
    __syncthreads();                   // tid 0's ticket happens-after all fences
    __shared__ unsigned int s_last;
    if (tid == 0) {
        unsigned int t = atomicAdd(&g_ticket, 1u);
        s_last = (t == (unsigned int)(NB - 1)) ? 1u : 0u;
    }
    __syncthreads();
    if (!s_last) return;

    // Elected last block: all blocks' atomics are visible in L2.
    // 256 threads, 2 columns each; fold the two shadows.
    float d0 = __ldcg(&g_diag_pad[0][tid * PAD])
             + __ldcg(&g_diag_pad[1][tid * PAD]);
    float d1 = __ldcg(&g_diag_pad[0][(tid + 256) * PAD])
             + __ldcg(&g_diag_pad[1][(tid + 256) * PAD]);
    double r0 = (double)d0 - 1.0;
    double r1 = (double)d1 - 1.0;

    // Reset accumulators for the next graph replay (visible at next launch
    // via stream ordering).
    g_diag_pad[0][tid * PAD]         = 0.f;
    g_diag_pad[1][tid * PAD]         = 0.f;
    g_diag_pad[0][(tid + 256) * PAD] = 0.f;
    g_diag_pad[1][(tid + 256) * PAD] = 0.f;

    __shared__ double sh[TPB];
    sh[tid] = r0 * r0 + r1 * r1;
    __syncthreads();
    #pragma unroll
    for (int off = TPB / 2; off > 0; off >>= 1) {
        if (tid < off) sh[tid] += sh[tid + off];
        __syncthreads();
    }

    if (tid == 0) {
        out[0] = (float)(0.001 * sqrt(sh[0]));
        g_ticket = 0u;                 // reset for next replay
    }
}

extern "C" void kernel_launch(void* const* d_in, const int* in_sizes, int n_in,
                              void* d_out, int out_size) {
    const float* D = (const float*)d_in[0];
    const int n = in_sizes[0] / D_COLS;     // rows
    float* out = (float*)d_out;

    colsq_fused_kernel<<<NB, TPB>>>(D, n, out);
}